// round 13
// baseline (speedup 1.0000x reference)
#include <cuda_runtime.h>
#include <cuda_fp16.h>
#include <math.h>
#include <stdint.h>

#define BB 2
#define NHALF 1024
#define SS 2048
#define DIM 768
#define NH 12
#define HD 64
#define COND 128
#define BLK 16
#define MTOT (BB*SS)          // 4096
#define MODS (6*DIM)          // 4608

// weight arena offsets (halves)
#define W_QKV 0
#define W_ATT (W_QKV + 3*DIM*DIM)
#define W_M1  (W_ATT + DIM*DIM)
#define W_M2  (W_M1 + 4*DIM*DIM)
#define W_TOT (W_M2 + 4*DIM*DIM)

// ---------------- scratch (device globals; no allocation allowed) ----------------
__device__ float g_mods[BB*MODS];
__device__ __half g_h16[MTOT*DIM];
__device__ __half g_qkv16[(size_t)MTOT*3*DIM];
__device__ __half g_a16[MTOT*DIM];
__device__ float g_x2[MTOT*DIM];
__device__ __half g_mlp16[(size_t)MTOT*4*DIM];
__device__ __half g_w16[W_TOT];

// ---------------- helpers ----------------
__device__ __forceinline__ float gelu_tanh(float x) {
    float x3 = x * x * x;
    return 0.5f * x * (1.f + tanhf(0.7978845608028654f * (x + 0.044715f * x3)));
}
__device__ __forceinline__ void mma_f16(float c[4], const uint32_t a[4], const uint32_t b[2]) {
    asm volatile(
        "mma.sync.aligned.m16n8k16.row.col.f32.f16.f16.f32 "
        "{%0,%1,%2,%3},{%4,%5,%6,%7},{%8,%9},{%0,%1,%2,%3};"
        : "+f"(c[0]), "+f"(c[1]), "+f"(c[2]), "+f"(c[3])
        : "r"(a[0]), "r"(a[1]), "r"(a[2]), "r"(a[3]), "r"(b[0]), "r"(b[1]));
}
__device__ __forceinline__ void ldsm4(uint32_t r[4], uint32_t addr) {
    asm volatile("ldmatrix.sync.aligned.m8n8.x4.shared.b16 {%0,%1,%2,%3}, [%4];"
                 : "=r"(r[0]), "=r"(r[1]), "=r"(r[2]), "=r"(r[3]) : "r"(addr));
}
__device__ __forceinline__ void ldsm2t(uint32_t r[2], uint32_t addr) {
    asm volatile("ldmatrix.sync.aligned.m8n8.x2.trans.shared.b16 {%0,%1}, [%2];"
                 : "=r"(r[0]), "=r"(r[1]) : "r"(addr));
}
__device__ __forceinline__ void cp16(uint32_t dst, const void* src) {
    asm volatile("cp.async.cg.shared.global [%0], [%1], 16;\n" :: "r"(dst), "l"(src));
}

// ---------------- weight fp32 -> fp16 conversion ----------------
__global__ void cvt_w_k(const float* __restrict__ w0, const float* __restrict__ w1,
                        const float* __restrict__ w2, const float* __restrict__ w3,
                        __half* __restrict__ dst) {
    int i4 = (blockIdx.x * 256 + threadIdx.x) * 4;
    if (i4 >= W_TOT) return;
    const float* src; int off;
    if (i4 < W_ATT)      { src = w0; off = i4 - W_QKV; }
    else if (i4 < W_M1)  { src = w1; off = i4 - W_ATT; }
    else if (i4 < W_M2)  { src = w2; off = i4 - W_M1; }
    else                 { src = w3; off = i4 - W_M2; }
    float4 v = *(const float4*)&src[off];
    *(half2*)&dst[i4]     = __floats2half2_rn(v.x, v.y);
    *(half2*)&dst[i4 + 2] = __floats2half2_rn(v.z, v.w);
}

// ---------------- adaLN: mods = c @ W^T + b ----------------
__global__ void adaln_k(const float* __restrict__ c, const float* __restrict__ w,
                        const float* __restrict__ b, float* __restrict__ mods) {
    int j = blockIdx.x * blockDim.x + threadIdx.x;
    if (j >= BB * MODS) return;
    int bb = j / MODS;
    int n  = j % MODS;
    const float* cr = c + bb * COND;
    const float* wr = w + (size_t)n * COND;
    float acc = b[n];
#pragma unroll 8
    for (int k = 0; k < COND; k++) acc += cr[k] * wr[k];
    mods[j] = acc;
}

// ---------------- LayerNorm + modulate -> fp16 ----------------
__global__ void ln_mod_k(const float* __restrict__ x, const float* __restrict__ w,
                         const float* __restrict__ mods, __half* __restrict__ out,
                         int shift_off, int scale_off) {
    int row = blockIdx.x;
    int bb  = row / SS;
    const float* xr = x + (size_t)row * DIM;
    int tid = threadIdx.x;

    float s = 0.f, s2 = 0.f;
    for (int j = tid; j < DIM; j += blockDim.x) {
        float v = xr[j];
        s += v; s2 += v * v;
    }
#pragma unroll
    for (int o = 16; o; o >>= 1) {
        s  += __shfl_xor_sync(0xffffffffu, s,  o);
        s2 += __shfl_xor_sync(0xffffffffu, s2, o);
    }
    __shared__ float wsum[8], wsum2[8];
    __shared__ float s_mu, s_rv;
    if ((tid & 31) == 0) { wsum[tid >> 5] = s; wsum2[tid >> 5] = s2; }
    __syncthreads();
    if (tid == 0) {
        float t = 0.f, t2 = 0.f;
        for (int i = 0; i < 8; i++) { t += wsum[i]; t2 += wsum2[i]; }
        float mu = t / DIM;
        float var = t2 / DIM - mu * mu;
        s_mu = mu;
        s_rv = rsqrtf(var + 1e-5f);
    }
    __syncthreads();
    float mu = s_mu, rv = s_rv;
    const float* msh = mods + bb * MODS + shift_off;
    const float* msc = mods + bb * MODS + scale_off;
    __half* orow = out + (size_t)row * DIM;
    for (int j = tid; j < DIM; j += blockDim.x)
        orow[j] = __float2half((xr[j] - mu) * rv * w[j] * (1.f + msc[j]) + msh[j]);
}

// ---------------- fp16 TC GEMM: 8 warps, ldmatrix, BK=64, 2-stage, 1 sync/iter ----------------
#define AST 72                 // halves per smem row (144B pitch, LDSM conflict-free)
#define STG_A 18432            // bytes: 128 rows x 72 halves
#define STG_TOT 36864          // A + B per stage
#define NSTG 2
#define DYN_SMEM (NSTG * STG_TOT)   // 73728 B

__global__ __launch_bounds__(256, 2) void gemm_h_k(
    const __half* __restrict__ A, const __half* __restrict__ Bw,
    float* __restrict__ Cf, __half* __restrict__ Ch,
    int M, int Ncols, int K,
    const float* __restrict__ bias, const float* __restrict__ res,
    const float* __restrict__ mods, int gate_off, int mode,
    const float* __restrict__ cosb, const float* __restrict__ sinb) {
    extern __shared__ __half dynsm[];
    int tid  = threadIdx.x;
    int wid  = tid >> 5, lane = tid & 31;
    int wm   = wid >> 2, wn = wid & 3;       // 2x4 warp grid
    int g    = lane >> 2, t = lane & 3;
    int m0   = blockIdx.y * 128, n0 = blockIdx.x * 128;

    uint32_t smBase = (uint32_t)__cvta_generic_to_shared(dynsm);

    int quad = lane >> 3, lr = lane & 7;
    int aRowOff = lr + (quad & 1) * 8;
    int aColOff = (quad >> 1) * 8;
    int bRowOff = wn * 8 + (quad >> 1) * 32 + lr;
    int bColOff = (quad & 1) * 8;

    float acc[4][4][4];
#pragma unroll
    for (int i = 0; i < 4; i++)
#pragma unroll
        for (int j = 0; j < 4; j++)
#pragma unroll
            for (int r = 0; r < 4; r++) acc[i][j][r] = 0.f;

    int nIter = K >> 6;   // BK = 64
#define PREFETCH(it, s) {                                                           \
        int k0 = (it) << 6;                                                         \
        uint32_t aDst = smBase + (s) * STG_TOT;                                     \
        uint32_t bDst = aDst + STG_A;                                               \
        _Pragma("unroll")                                                           \
        for (int i = 0; i < 4; i++) {                                               \
            int e = i * 256 + tid;                                                  \
            int r = e >> 3, cc = (e & 7) * 8;                                       \
            cp16(aDst + (r * AST + cc) * 2, A + (size_t)(m0 + r) * K + k0 + cc);    \
            cp16(bDst + (r * AST + cc) * 2, Bw + (size_t)(n0 + r) * K + k0 + cc);   \
        }                                                                           \
        asm volatile("cp.async.commit_group;\n");                                   \
    }

    PREFETCH(0, 0);
    for (int it = 0; it < nIter; it++) {
        asm volatile("cp.async.wait_group 0;\n");
        __syncthreads();
        if (it + 1 < nIter) PREFETCH(it + 1, (it + 1) & 1);

        uint32_t aS = smBase + (it & 1) * STG_TOT;
        uint32_t bS = aS + STG_A;
#pragma unroll
        for (int ks = 0; ks < 4; ks++) {
            int kb = ks * 16;
            uint32_t af[4][4], bf[4][2];
#pragma unroll
            for (int mt = 0; mt < 4; mt++) {
                int r = wm * 64 + mt * 16 + aRowOff;
                ldsm4(af[mt], aS + (r * AST + kb + aColOff) * 2);
            }
#pragma unroll
            for (int p = 0; p < 2; p++) {
                uint32_t tmp[4];
                int r = p * 64 + bRowOff;
                ldsm4(tmp, bS + (r * AST + kb + bColOff) * 2);
                bf[2 * p][0] = tmp[0]; bf[2 * p][1] = tmp[1];
                bf[2 * p + 1][0] = tmp[2]; bf[2 * p + 1][1] = tmp[3];
            }
#pragma unroll
            for (int mt = 0; mt < 4; mt++)
#pragma unroll
                for (int nt = 0; nt < 4; nt++) mma_f16(acc[mt][nt], af[mt], bf[nt]);
        }
    }

    // ---- epilogue ----
#pragma unroll
    for (int mt = 0; mt < 4; mt++) {
#pragma unroll
        for (int half_ = 0; half_ < 2; half_++) {
            int m = m0 + wm * 64 + mt * 16 + half_ * 8 + g;
            int bb = m / SS;
            if (mode == 3) {
                int stok = m & (SS - 1);
#pragma unroll
                for (int p = 0; p < 2; p++) {
                    int d0 = wn * 8 + 2 * t;
                    int n = n0 + p * 64 + d0;
                    float y1[2], y2[2];
#pragma unroll
                    for (int j = 0; j < 2; j++) {
                        float x1 = acc[mt][2 * p][half_ * 2 + j];
                        float x2 = acc[mt][2 * p + 1][half_ * 2 + j];
                        float c1 = cosb[stok * HD + d0 + j];
                        float s1 = sinb[stok * HD + d0 + j];
                        float c2 = cosb[stok * HD + d0 + j + 32];
                        float s2 = sinb[stok * HD + d0 + j + 32];
                        y1[j] = x1 * c1 - x2 * s1;
                        y2[j] = x2 * c2 + x1 * s2;
                    }
                    *(half2*)&Ch[(size_t)m * Ncols + n]      = __floats2half2_rn(y1[0], y1[1]);
                    *(half2*)&Ch[(size_t)m * Ncols + n + 32] = __floats2half2_rn(y2[0], y2[1]);
                }
            } else {
#pragma unroll
                for (int nt = 0; nt < 4; nt++) {
                    int n = n0 + wn * 8 + (nt & 1) * 32 + (nt >> 1) * 64 + 2 * t;
                    float v0 = acc[mt][nt][half_ * 2 + 0];
                    float v1 = acc[mt][nt][half_ * 2 + 1];
                    if (mode == 1) {
                        v0 = gelu_tanh(v0 + bias[n]);
                        v1 = gelu_tanh(v1 + bias[n + 1]);
                        *(half2*)&Ch[(size_t)m * Ncols + n] = __floats2half2_rn(v0, v1);
                    } else {  // mode 2
                        if (bias) { v0 += bias[n]; v1 += bias[n + 1]; }
                        float g0 = mods[bb * MODS + gate_off + n];
                        float g1 = mods[bb * MODS + gate_off + n + 1];
                        v0 = res[(size_t)m * Ncols + n]     + g0 * v0;
                        v1 = res[(size_t)m * Ncols + n + 1] + g1 * v1;
                        *(float2*)&Cf[(size_t)m * Ncols + n] = make_float2(v0, v1);
                    }
                }
            }
        }
    }
}

// ---------------- Block-sparse flash attention: fp16 qkv, 128-key chunks ----------------
// Key list per CTA = [prefix: blkq*16 half-2 keys][own 16 half-1][own 16 half-2].
#define QP 72
#define KP 72
#define PP 136   // P pitch (halves); P aliases Ks rows 0..31

__global__ __launch_bounds__(256, 2) void attn_mma_k(const __half* __restrict__ qkv,
                                                     __half* __restrict__ out) {
    int blkq = 63 - blockIdx.x;          // heavy CTAs first
    int bh = blockIdx.y;
    int bb = bh / NH, hh = bh % NH;
    int q0a = blkq * BLK;
    int q0b = NHALF + blkq * BLK;

    __shared__ __half Qs[32 * QP];
    __shared__ __half Ks[128 * KP];
    __shared__ __half Vs[128 * KP];
    __shared__ float redmax[32][9];
    __shared__ float redsum[32][9];
    __half* Ps = Ks;
    uint32_t vsBase = (uint32_t)__cvta_generic_to_shared(Vs);

    int tid = threadIdx.x;
    int w = tid >> 5, lane = tid & 31;
    int g = lane >> 2, t = lane & 3;
    int ksl = w * 16;                    // QK: 16-key slice
    int sl  = w * 8;                     // PV/out: 8-wide d slice

    // load Q (32 x 64 fp16): 256 uint4
    {
        int e = tid;
        int r = e >> 3, d8 = (e & 7) * 8;
        int qg = (r < 16) ? (q0a + r) : (q0b + r - 16);
        *(uint4*)&Qs[r * QP + d8] =
            *(const uint4*)&qkv[(((size_t)(bb * SS + qg) * 3 + 0) * NH + hh) * HD + d8];
    }

    float m_st[4], l_st[4];
#pragma unroll
    for (int i = 0; i < 4; i++) { m_st[i] = -1e30f; l_st[i] = 0.f; }
    float co[2][4] = {};

    int L = blkq * BLK;           // prefix keys
    int TOT = L + 32;
    int nch = (TOT + 127) >> 7;
    for (int ch = 0; ch < nch; ch++) {
        int base = ch << 7;
        int len = min(128, TOT - base);
        __syncthreads();           // prev chunk PV/P reads done
        for (int e = tid; e < len * 8; e += 256) {
            int r = e >> 3, d8 = (e & 7) * 8;
            int j = base + r;
            int kg = (j < L) ? (NHALF + j)
                             : ((j - L < 16) ? (q0a + j - L) : (q0b + j - L - 16));
            size_t gb = ((size_t)(bb * SS + kg) * 3 + 1) * (NH * HD) + (size_t)hh * HD + d8;
            *(uint4*)&Ks[r * KP + d8] = *(const uint4*)&qkv[gb];
            *(uint4*)&Vs[r * KP + d8] = *(const uint4*)&qkv[gb + NH * HD];
        }
        for (int e = tid; e < (128 - len) * 8; e += 256) {   // zero V pad rows
            int r = len + (e >> 3), d8 = (e & 7) * 8;
            *(uint4*)&Vs[r * KP + d8] = make_uint4(0, 0, 0, 0);
        }
        __syncthreads();

        // ---- QK: 32 x 128; warp owns keys [ksl, ksl+16) ----
        float cqk[2][2][4] = {};
#pragma unroll
        for (int kd = 0; kd < 4; kd++) {
            int kb = kd * 16;
            uint32_t af[2][4];
#pragma unroll
            for (int mf = 0; mf < 2; mf++) {
                int rm = mf * 16;
                af[mf][0] = *(const uint32_t*)&Qs[(rm + g) * QP + kb + 2 * t];
                af[mf][1] = *(const uint32_t*)&Qs[(rm + g + 8) * QP + kb + 2 * t];
                af[mf][2] = *(const uint32_t*)&Qs[(rm + g) * QP + kb + 2 * t + 8];
                af[mf][3] = *(const uint32_t*)&Qs[(rm + g + 8) * QP + kb + 2 * t + 8];
            }
#pragma unroll
            for (int o = 0; o < 2; o++) {
                uint32_t bf[2];
                int rn = ksl + o * 8 + g;
                bf[0] = *(const uint32_t*)&Ks[rn * KP + kb + 2 * t];
                bf[1] = *(const uint32_t*)&Ks[rn * KP + kb + 2 * t + 8];
#pragma unroll
                for (int mf = 0; mf < 2; mf++) mma_f16(cqk[mf][o], af[mf], bf);
            }
        }
        // mask + scale in place
#pragma unroll
        for (int mf = 0; mf < 2; mf++)
#pragma unroll
            for (int o = 0; o < 2; o++)
#pragma unroll
                for (int idx = 0; idx < 4; idx++) {
                    int j = base + ksl + o * 8 + 2 * t + (idx & 1);
                    int row = mf * 16 + g + 8 * (idx >> 1);
                    bool valid;
                    if (j < L) valid = true;
                    else {
                        int loc = j - L;
                        valid = (loc < 32) && ((row < 16) == (loc < 16));
                    }
                    cqk[mf][o][idx] = valid ? cqk[mf][o][idx] * 0.125f : -1e30f;
                }
        // per-row warp max
        float rmax[4];
#pragma unroll
        for (int mf = 0; mf < 2; mf++)
#pragma unroll
            for (int h = 0; h < 2; h++)
                rmax[mf * 2 + h] = fmaxf(fmaxf(cqk[mf][0][2 * h], cqk[mf][0][2 * h + 1]),
                                         fmaxf(cqk[mf][1][2 * h], cqk[mf][1][2 * h + 1]));
#pragma unroll
        for (int i = 0; i < 4; i++) {
            rmax[i] = fmaxf(rmax[i], __shfl_xor_sync(0xffffffffu, rmax[i], 1));
            rmax[i] = fmaxf(rmax[i], __shfl_xor_sync(0xffffffffu, rmax[i], 2));
        }
        if (t == 0)
#pragma unroll
            for (int i = 0; i < 4; i++)
                redmax[(i >> 1) * 16 + (i & 1) * 8 + g][w] = rmax[i];
        __syncthreads();   // redmax visible; Ks reads done -> Ps alias safe

        float mnew[4], corr[4];
#pragma unroll
        for (int i = 0; i < 4; i++) {
            int row = (i >> 1) * 16 + (i & 1) * 8 + g;
            float cm = -1e30f;
#pragma unroll
            for (int w2 = 0; w2 < 8; w2++) cm = fmaxf(cm, redmax[row][w2]);
            mnew[i] = fmaxf(m_st[i], cm);
            corr[i] = __expf(m_st[i] - mnew[i]);
            m_st[i] = mnew[i];
        }
        float psum[4] = {0.f, 0.f, 0.f, 0.f};
#pragma unroll
        for (int mf = 0; mf < 2; mf++)
#pragma unroll
            for (int h = 0; h < 2; h++) {
                int i = mf * 2 + h;
                int row = mf * 16 + h * 8 + g;
#pragma unroll
                for (int o = 0; o < 2; o++) {
                    float p0 = __expf(cqk[mf][o][2 * h]     - mnew[i]);
                    float p1 = __expf(cqk[mf][o][2 * h + 1] - mnew[i]);
                    psum[i] += p0 + p1;
                    *(half2*)&Ps[row * PP + ksl + o * 8 + 2 * t] = __floats2half2_rn(p0, p1);
                }
            }
#pragma unroll
        for (int i = 0; i < 4; i++) {
            psum[i] += __shfl_xor_sync(0xffffffffu, psum[i], 1);
            psum[i] += __shfl_xor_sync(0xffffffffu, psum[i], 2);
        }
        if (t == 0)
#pragma unroll
            for (int i = 0; i < 4; i++)
                redsum[(i >> 1) * 16 + (i & 1) * 8 + g][w] = psum[i];
        __syncthreads();

#pragma unroll
        for (int i = 0; i < 4; i++) {
            int row = (i >> 1) * 16 + (i & 1) * 8 + g;
            float tot = 0.f;
#pragma unroll
            for (int w2 = 0; w2 < 8; w2++) tot += redsum[row][w2];
            l_st[i] = l_st[i] * corr[i] + tot;
        }
#pragma unroll
        for (int mf = 0; mf < 2; mf++)
#pragma unroll
            for (int idx = 0; idx < 4; idx++)
                co[mf][idx] *= corr[mf * 2 + (idx >> 1)];
        // ---- PV: warp owns d slice [sl, sl+8) ----
#pragma unroll
        for (int kk = 0; kk < 8; kk++) {
            int kb = kk * 16;
            uint32_t bf[2];
            ldsm2t(bf, vsBase + ((kb + (lane & 15)) * KP + sl) * 2);
#pragma unroll
            for (int mf = 0; mf < 2; mf++) {
                uint32_t af[4];
                int rm = mf * 16;
                af[0] = *(const uint32_t*)&Ps[(rm + g) * PP + kb + 2 * t];
                af[1] = *(const uint32_t*)&Ps[(rm + g + 8) * PP + kb + 2 * t];
                af[2] = *(const uint32_t*)&Ps[(rm + g) * PP + kb + 2 * t + 8];
                af[3] = *(const uint32_t*)&Ps[(rm + g + 8) * PP + kb + 2 * t + 8];
                mma_f16(co[mf], af, bf);
            }
        }
    }

#pragma unroll
    for (int mf = 0; mf < 2; mf++)
#pragma unroll
        for (int h = 0; h < 2; h++) {
            int row = mf * 16 + 8 * h + g;
            int qg = (row < 16) ? (q0a + row) : (q0b + row - 16);
            float inv = 1.f / l_st[mf * 2 + h];
            *(half2*)&out[((size_t)bb * SS + qg) * DIM + hh * HD + sl + 2 * t] =
                __floats2half2_rn(co[mf][2 * h] * inv, co[mf][2 * h + 1] * inv);
        }
}

// ---------------- launch ----------------
extern "C" void kernel_launch(void* const* d_in, const int* in_sizes, int n_in,
                              void* d_out, int out_size) {
    const float* x        = (const float*)d_in[0];
    const float* c        = (const float*)d_in[1];
    const float* cosb     = (const float*)d_in[2];
    const float* sinb     = (const float*)d_in[3];
    /* d_in[4] = mask (recomputed analytically in-kernel) */
    const float* norm1_w  = (const float*)d_in[5];
    const float* qkv_w    = (const float*)d_in[6];
    const float* attn_w   = (const float*)d_in[7];
    const float* norm2_w  = (const float*)d_in[8];
    const float* mlp_w1   = (const float*)d_in[9];
    const float* mlp_b1   = (const float*)d_in[10];
    const float* mlp_w2   = (const float*)d_in[11];
    const float* mlp_b2   = (const float*)d_in[12];
    const float* adaLN_w  = (const float*)d_in[13];
    const float* adaLN_b  = (const float*)d_in[14];
    float* out = (float*)d_out;

    float *mods, *x2;
    __half *h16, *qkv16, *a16, *mlp16, *w16;
    cudaGetSymbolAddress((void**)&mods,   g_mods);
    cudaGetSymbolAddress((void**)&h16,    g_h16);
    cudaGetSymbolAddress((void**)&qkv16,  g_qkv16);
    cudaGetSymbolAddress((void**)&a16,    g_a16);
    cudaGetSymbolAddress((void**)&x2,     g_x2);
    cudaGetSymbolAddress((void**)&mlp16,  g_mlp16);
    cudaGetSymbolAddress((void**)&w16,    g_w16);

    cudaFuncSetAttribute(gemm_h_k, cudaFuncAttributeMaxDynamicSharedMemorySize, DYN_SMEM);

    // 0. convert weights to fp16 arena
    cvt_w_k<<<(W_TOT / 4 + 255) / 256, 256>>>(qkv_w, attn_w, mlp_w1, mlp_w2, w16);

    // 1. adaLN modulation vector
    adaln_k<<<(BB * MODS + 255) / 256, 256>>>(c, adaLN_w, adaLN_b, mods);

    // 2. norm1 + modulate -> fp16
    ln_mod_k<<<MTOT, 256>>>(x, norm1_w, mods, h16, 0, DIM);

    // 3. QKV projection + fused RoPE (mode 3) -> fp16 qkv
    gemm_h_k<<<dim3(3 * DIM / 128, MTOT / 128), 256, DYN_SMEM>>>(
        h16, w16 + W_QKV, nullptr, qkv16, MTOT, 3 * DIM, DIM,
        nullptr, nullptr, nullptr, 0, 3, cosb, sinb);

    // 4. Block-sparse flash attention (fp16 MMA, 128-key chunks) -> fp16 a
    attn_mma_k<<<dim3(64, BB * NH), 256>>>(qkv16, a16);

    // 5. attn-out projection + gate_msa + x residual -> fp32 x2
    gemm_h_k<<<dim3(DIM / 128, MTOT / 128), 256, DYN_SMEM>>>(
        a16, w16 + W_ATT, x2, nullptr, MTOT, DIM, DIM,
        nullptr, x, mods, 2 * DIM, 2, nullptr, nullptr);

    // 6. norm2 + modulate -> fp16
    ln_mod_k<<<MTOT, 256>>>(x2, norm2_w, mods, h16, 3 * DIM, 4 * DIM);

    // 7. MLP up + gelu (mode 1) -> fp16 mlp
    gemm_h_k<<<dim3(4 * DIM / 128, MTOT / 128), 256, DYN_SMEM>>>(
        h16, w16 + W_M1, nullptr, mlp16, MTOT, 4 * DIM, DIM,
        mlp_b1, nullptr, nullptr, 0, 1, nullptr, nullptr);

    // 8. MLP down + bias + gate_mlp + x2 residual -> d_out
    gemm_h_k<<<dim3(DIM / 128, MTOT / 128), 256, DYN_SMEM>>>(
        mlp16, w16 + W_M2, out, nullptr, MTOT, DIM, 4 * DIM,
        mlp_b2, x2, mods, 5 * DIM, 2, nullptr, nullptr);
}

// round 14
// speedup vs baseline: 1.3859x; 1.3859x over previous
#include <cuda_runtime.h>
#include <cuda_fp16.h>
#include <math.h>
#include <stdint.h>

#define BB 2
#define NHALF 1024
#define SS 2048
#define DIM 768
#define NH 12
#define HD 64
#define COND 128
#define BLK 16
#define MTOT (BB*SS)          // 4096
#define MODS (6*DIM)          // 4608

// weight arena offsets (halves)
#define W_QKV 0
#define W_ATT (W_QKV + 3*DIM*DIM)
#define W_M1  (W_ATT + DIM*DIM)
#define W_M2  (W_M1 + 4*DIM*DIM)
#define W_TOT (W_M2 + 4*DIM*DIM)

// ---------------- scratch (device globals; no allocation allowed) ----------------
__device__ float g_mods[BB*MODS];
__device__ __half g_h16[MTOT*DIM];
__device__ float g_qkv[(size_t)MTOT*3*DIM];
__device__ __half g_a16[MTOT*DIM];
__device__ float g_x2[MTOT*DIM];
__device__ __half g_mlp16[(size_t)MTOT*4*DIM];
__device__ __half g_w16[W_TOT];

// ---------------- helpers ----------------
__device__ __forceinline__ float gelu_tanh(float x) {
    float x3 = x * x * x;
    return 0.5f * x * (1.f + tanhf(0.7978845608028654f * (x + 0.044715f * x3)));
}
__device__ __forceinline__ void mma_f16(float c[4], const uint32_t a[4], const uint32_t b[2]) {
    asm volatile(
        "mma.sync.aligned.m16n8k16.row.col.f32.f16.f16.f32 "
        "{%0,%1,%2,%3},{%4,%5,%6,%7},{%8,%9},{%0,%1,%2,%3};"
        : "+f"(c[0]), "+f"(c[1]), "+f"(c[2]), "+f"(c[3])
        : "r"(a[0]), "r"(a[1]), "r"(a[2]), "r"(a[3]), "r"(b[0]), "r"(b[1]));
}
__device__ __forceinline__ void ldsm4(uint32_t r[4], uint32_t addr) {
    asm volatile("ldmatrix.sync.aligned.m8n8.x4.shared.b16 {%0,%1,%2,%3}, [%4];"
                 : "=r"(r[0]), "=r"(r[1]), "=r"(r[2]), "=r"(r[3]) : "r"(addr));
}
__device__ __forceinline__ void ldsm2t(uint32_t r[2], uint32_t addr) {
    asm volatile("ldmatrix.sync.aligned.m8n8.x2.trans.shared.b16 {%0,%1}, [%2];"
                 : "=r"(r[0]), "=r"(r[1]) : "r"(addr));
}
__device__ __forceinline__ void cp16(uint32_t dst, const void* src) {
    asm volatile("cp.async.cg.shared.global [%0], [%1], 16;\n" :: "r"(dst), "l"(src));
}

// ---------------- weight fp32 -> fp16 conversion ----------------
__global__ void cvt_w_k(const float* __restrict__ w0, const float* __restrict__ w1,
                        const float* __restrict__ w2, const float* __restrict__ w3,
                        __half* __restrict__ dst) {
    int i4 = (blockIdx.x * 256 + threadIdx.x) * 4;
    if (i4 >= W_TOT) return;
    const float* src; int off;
    if (i4 < W_ATT)      { src = w0; off = i4 - W_QKV; }
    else if (i4 < W_M1)  { src = w1; off = i4 - W_ATT; }
    else if (i4 < W_M2)  { src = w2; off = i4 - W_M1; }
    else                 { src = w3; off = i4 - W_M2; }
    float4 v = *(const float4*)&src[off];
    *(half2*)&dst[i4]     = __floats2half2_rn(v.x, v.y);
    *(half2*)&dst[i4 + 2] = __floats2half2_rn(v.z, v.w);
}

// ---------------- adaLN: mods = c @ W^T + b ----------------
__global__ void adaln_k(const float* __restrict__ c, const float* __restrict__ w,
                        const float* __restrict__ b, float* __restrict__ mods) {
    int j = blockIdx.x * blockDim.x + threadIdx.x;
    if (j >= BB * MODS) return;
    int bb = j / MODS;
    int n  = j % MODS;
    const float* cr = c + bb * COND;
    const float* wr = w + (size_t)n * COND;
    float acc = b[n];
#pragma unroll 8
    for (int k = 0; k < COND; k++) acc += cr[k] * wr[k];
    mods[j] = acc;
}

// ---------------- LayerNorm + modulate -> fp16 ----------------
__global__ void ln_mod_k(const float* __restrict__ x, const float* __restrict__ w,
                         const float* __restrict__ mods, __half* __restrict__ out,
                         int shift_off, int scale_off) {
    int row = blockIdx.x;
    int bb  = row / SS;
    const float* xr = x + (size_t)row * DIM;
    int tid = threadIdx.x;

    float s = 0.f, s2 = 0.f;
    for (int j = tid; j < DIM; j += blockDim.x) {
        float v = xr[j];
        s += v; s2 += v * v;
    }
#pragma unroll
    for (int o = 16; o; o >>= 1) {
        s  += __shfl_xor_sync(0xffffffffu, s,  o);
        s2 += __shfl_xor_sync(0xffffffffu, s2, o);
    }
    __shared__ float wsum[8], wsum2[8];
    __shared__ float s_mu, s_rv;
    if ((tid & 31) == 0) { wsum[tid >> 5] = s; wsum2[tid >> 5] = s2; }
    __syncthreads();
    if (tid == 0) {
        float t = 0.f, t2 = 0.f;
        for (int i = 0; i < 8; i++) { t += wsum[i]; t2 += wsum2[i]; }
        float mu = t / DIM;
        float var = t2 / DIM - mu * mu;
        s_mu = mu;
        s_rv = rsqrtf(var + 1e-5f);
    }
    __syncthreads();
    float mu = s_mu, rv = s_rv;
    const float* msh = mods + bb * MODS + shift_off;
    const float* msc = mods + bb * MODS + scale_off;
    __half* orow = out + (size_t)row * DIM;
    for (int j = tid; j < DIM; j += blockDim.x)
        orow[j] = __float2half((xr[j] - mu) * rv * w[j] * (1.f + msc[j]) + msh[j]);
}

// ---------------- fp16 TC GEMM: 8 warps, ldmatrix, BK=64, 2-stage, 1 sync/iter ----------------
#define AST 72                 // halves per smem row (144B pitch, LDSM conflict-free)
#define STG_A 18432            // bytes: 128 rows x 72 halves
#define STG_TOT 36864          // A + B per stage
#define NSTG 2
#define DYN_SMEM (NSTG * STG_TOT)   // 73728 B

__global__ __launch_bounds__(256, 2) void gemm_h_k(
    const __half* __restrict__ A, const __half* __restrict__ Bw,
    float* __restrict__ Cf, __half* __restrict__ Ch,
    int M, int Ncols, int K,
    const float* __restrict__ bias, const float* __restrict__ res,
    const float* __restrict__ mods, int gate_off, int mode,
    const float* __restrict__ cosb, const float* __restrict__ sinb) {
    extern __shared__ __half dynsm[];
    int tid  = threadIdx.x;
    int wid  = tid >> 5, lane = tid & 31;
    int wm   = wid >> 2, wn = wid & 3;       // 2x4 warp grid
    int g    = lane >> 2, t = lane & 3;
    int m0   = blockIdx.y * 128, n0 = blockIdx.x * 128;

    uint32_t smBase = (uint32_t)__cvta_generic_to_shared(dynsm);

    int quad = lane >> 3, lr = lane & 7;
    int aRowOff = lr + (quad & 1) * 8;
    int aColOff = (quad >> 1) * 8;
    int bRowOff = wn * 8 + (quad >> 1) * 32 + lr;
    int bColOff = (quad & 1) * 8;

    float acc[4][4][4];
#pragma unroll
    for (int i = 0; i < 4; i++)
#pragma unroll
        for (int j = 0; j < 4; j++)
#pragma unroll
            for (int r = 0; r < 4; r++) acc[i][j][r] = 0.f;

    int nIter = K >> 6;   // BK = 64
#define PREFETCH(it, s) {                                                           \
        int k0 = (it) << 6;                                                         \
        uint32_t aDst = smBase + (s) * STG_TOT;                                     \
        uint32_t bDst = aDst + STG_A;                                               \
        _Pragma("unroll")                                                           \
        for (int i = 0; i < 4; i++) {                                               \
            int e = i * 256 + tid;                                                  \
            int r = e >> 3, cc = (e & 7) * 8;                                       \
            cp16(aDst + (r * AST + cc) * 2, A + (size_t)(m0 + r) * K + k0 + cc);    \
            cp16(bDst + (r * AST + cc) * 2, Bw + (size_t)(n0 + r) * K + k0 + cc);   \
        }                                                                           \
        asm volatile("cp.async.commit_group;\n");                                   \
    }

    PREFETCH(0, 0);
    for (int it = 0; it < nIter; it++) {
        asm volatile("cp.async.wait_group 0;\n");
        __syncthreads();
        if (it + 1 < nIter) PREFETCH(it + 1, (it + 1) & 1);

        uint32_t aS = smBase + (it & 1) * STG_TOT;
        uint32_t bS = aS + STG_A;
#pragma unroll
        for (int ks = 0; ks < 4; ks++) {
            int kb = ks * 16;
            uint32_t af[4][4], bf[4][2];
#pragma unroll
            for (int mt = 0; mt < 4; mt++) {
                int r = wm * 64 + mt * 16 + aRowOff;
                ldsm4(af[mt], aS + (r * AST + kb + aColOff) * 2);
            }
#pragma unroll
            for (int p = 0; p < 2; p++) {
                uint32_t tmp[4];
                int r = p * 64 + bRowOff;
                ldsm4(tmp, bS + (r * AST + kb + bColOff) * 2);
                bf[2 * p][0] = tmp[0]; bf[2 * p][1] = tmp[1];
                bf[2 * p + 1][0] = tmp[2]; bf[2 * p + 1][1] = tmp[3];
            }
#pragma unroll
            for (int mt = 0; mt < 4; mt++)
#pragma unroll
                for (int nt = 0; nt < 4; nt++) mma_f16(acc[mt][nt], af[mt], bf[nt]);
        }
    }

    // ---- epilogue ----
#pragma unroll
    for (int mt = 0; mt < 4; mt++) {
#pragma unroll
        for (int half_ = 0; half_ < 2; half_++) {
            int m = m0 + wm * 64 + mt * 16 + half_ * 8 + g;
            int bb = m / SS;
            if (mode == 3) {
                int stok = m & (SS - 1);
#pragma unroll
                for (int p = 0; p < 2; p++) {
                    int d0 = wn * 8 + 2 * t;
                    int n = n0 + p * 64 + d0;
                    float y1[2], y2[2];
#pragma unroll
                    for (int j = 0; j < 2; j++) {
                        float x1 = acc[mt][2 * p][half_ * 2 + j];
                        float x2 = acc[mt][2 * p + 1][half_ * 2 + j];
                        float c1 = cosb[stok * HD + d0 + j];
                        float s1 = sinb[stok * HD + d0 + j];
                        float c2 = cosb[stok * HD + d0 + j + 32];
                        float s2 = sinb[stok * HD + d0 + j + 32];
                        y1[j] = x1 * c1 - x2 * s1;
                        y2[j] = x2 * c2 + x1 * s2;
                    }
                    *(float2*)&Cf[(size_t)m * Ncols + n]      = make_float2(y1[0], y1[1]);
                    *(float2*)&Cf[(size_t)m * Ncols + n + 32] = make_float2(y2[0], y2[1]);
                }
            } else {
#pragma unroll
                for (int nt = 0; nt < 4; nt++) {
                    int n = n0 + wn * 8 + (nt & 1) * 32 + (nt >> 1) * 64 + 2 * t;
                    float v0 = acc[mt][nt][half_ * 2 + 0];
                    float v1 = acc[mt][nt][half_ * 2 + 1];
                    if (mode == 1) {
                        v0 = gelu_tanh(v0 + bias[n]);
                        v1 = gelu_tanh(v1 + bias[n + 1]);
                        *(half2*)&Ch[(size_t)m * Ncols + n] = __floats2half2_rn(v0, v1);
                    } else {  // mode 2
                        if (bias) { v0 += bias[n]; v1 += bias[n + 1]; }
                        float g0 = mods[bb * MODS + gate_off + n];
                        float g1 = mods[bb * MODS + gate_off + n + 1];
                        v0 = res[(size_t)m * Ncols + n]     + g0 * v0;
                        v1 = res[(size_t)m * Ncols + n + 1] + g1 * v1;
                        *(float2*)&Cf[(size_t)m * Ncols + n] = make_float2(v0, v1);
                    }
                }
            }
        }
    }
}

// ---------------- Block-sparse flash attention (fp16 MMA, V linear + ldsm2t) ----------------
#define QSTH 72
#define KSTH 72
#define PSTH 72
#define VSTH 72   // V pitch, layout [key][d]

__global__ __launch_bounds__(256) void attn_mma_k(const float* __restrict__ qkv,
                                                  __half* __restrict__ out) {
    int blkq = 63 - blockIdx.x;          // heavy CTAs first
    int bh = blockIdx.y;
    int bb = bh / NH, hh = bh % NH;
    int q0a = blkq * BLK;
    int q0b = NHALF + blkq * BLK;

    __shared__ __half Qs[32 * QSTH];
    __shared__ __half Ks[64 * KSTH];     // P (32 x PSTH) aliases after QK reads
    __shared__ __half Vs[64 * VSTH];     // [key][d]
    __shared__ float redmax[32][9];
    __shared__ float redsum[32][9];
    __half* Ps = Ks;
    uint32_t vsBase = (uint32_t)__cvta_generic_to_shared(Vs);

    int tid = threadIdx.x;
    int w = tid >> 5, lane = tid & 31;
    int g = lane >> 2, t = lane & 3;
    int sl = w * 8;

    for (int e = tid; e < 32 * 16; e += 256) {
        int r = e >> 4, d4 = (e & 15) * 4;
        int qg = (r < 16) ? (q0a + r) : (q0b + r - 16);
        float4 v = *(const float4*)&qkv[((((size_t)bb * SS + qg) * 3 + 0) * NH + hh) * HD + d4];
        *(half2*)&Qs[r * QSTH + d4]     = __floats2half2_rn(v.x, v.y);
        *(half2*)&Qs[r * QSTH + d4 + 2] = __floats2half2_rn(v.z, v.w);
    }

    float m_st[4], l_st[4];
#pragma unroll
    for (int i = 0; i < 4; i++) { m_st[i] = -1e30f; l_st[i] = 0.f; }
    float co[2][4] = {};

    int nch = 1 + (blkq * BLK + 63) / 64;
    for (int ch = 0; ch < nch; ch++) {
        int len = (ch == 0) ? 32 : min(64, blkq * BLK - (ch - 1) * 64);
        __syncthreads();
        for (int e = tid; e < len * 16; e += 256) {
            int r = e >> 4, d4 = (e & 15) * 4;
            int kg = (ch == 0) ? ((r < 16) ? (q0a + r) : (q0b + r - 16))
                               : (NHALF + (ch - 1) * 64 + r);
            size_t gb = (((size_t)bb * SS + kg) * 3) * NH * HD + (size_t)hh * HD + d4;
            float4 kv = *(const float4*)&qkv[gb + (size_t)NH * HD];
            float4 vv = *(const float4*)&qkv[gb + (size_t)2 * NH * HD];
            *(half2*)&Ks[r * KSTH + d4]     = __floats2half2_rn(kv.x, kv.y);
            *(half2*)&Ks[r * KSTH + d4 + 2] = __floats2half2_rn(kv.z, kv.w);
            // V linear [key][d]: one 8B vector store
            half2 va = __floats2half2_rn(vv.x, vv.y);
            half2 vb = __floats2half2_rn(vv.z, vv.w);
            uint2 vpack = make_uint2(*(uint32_t*)&va, *(uint32_t*)&vb);
            *(uint2*)&Vs[r * VSTH + d4] = vpack;
        }
        if (len < 64) {   // zero V pad rows
            for (int e = tid; e < (64 - len) * 16; e += 256) {
                int r = len + (e >> 4), d4 = (e & 15) * 4;
                *(uint2*)&Vs[r * VSTH + d4] = make_uint2(0, 0);
            }
        }
        __syncthreads();

        float cqk[2][4] = {};
#pragma unroll
        for (int kd = 0; kd < 4; kd++) {
            int kb = kd * 16;
            uint32_t bf[2];
            bf[0] = *(const uint32_t*)&Ks[(sl + g) * KSTH + kb + 2 * t];
            bf[1] = *(const uint32_t*)&Ks[(sl + g) * KSTH + kb + 2 * t + 8];
#pragma unroll
            for (int mf = 0; mf < 2; mf++) {
                uint32_t af[4];
                int rm = mf * 16;
                af[0] = *(const uint32_t*)&Qs[(rm + g) * QSTH + kb + 2 * t];
                af[1] = *(const uint32_t*)&Qs[(rm + g + 8) * QSTH + kb + 2 * t];
                af[2] = *(const uint32_t*)&Qs[(rm + g) * QSTH + kb + 2 * t + 8];
                af[3] = *(const uint32_t*)&Qs[(rm + g + 8) * QSTH + kb + 2 * t + 8];
                mma_f16(cqk[mf], af, bf);
            }
        }
        float sc[2][4];
#pragma unroll
        for (int mf = 0; mf < 2; mf++)
#pragma unroll
            for (int idx = 0; idx < 4; idx++) {
                int key = sl + 2 * t + (idx & 1);
                int row = mf * 16 + g + 8 * (idx >> 1);
                bool valid = (ch == 0) ? ((key < 32) && ((row < 16) == (key < 16)))
                                       : (key < len);
                sc[mf][idx] = valid ? cqk[mf][idx] * 0.125f : -1e30f;
            }
        float rmax[4];
#pragma unroll
        for (int mf = 0; mf < 2; mf++)
#pragma unroll
            for (int h = 0; h < 2; h++)
                rmax[mf * 2 + h] = fmaxf(sc[mf][2 * h], sc[mf][2 * h + 1]);
#pragma unroll
        for (int i = 0; i < 4; i++) {
            rmax[i] = fmaxf(rmax[i], __shfl_xor_sync(0xffffffffu, rmax[i], 1));
            rmax[i] = fmaxf(rmax[i], __shfl_xor_sync(0xffffffffu, rmax[i], 2));
        }
        if (t == 0)
#pragma unroll
            for (int i = 0; i < 4; i++)
                redmax[(i >> 1) * 16 + (i & 1) * 8 + g][w] = rmax[i];
        __syncthreads();

        float mnew[4], corr[4];
#pragma unroll
        for (int i = 0; i < 4; i++) {
            int row = (i >> 1) * 16 + (i & 1) * 8 + g;
            float cm = -1e30f;
#pragma unroll
            for (int w2 = 0; w2 < 8; w2++) cm = fmaxf(cm, redmax[row][w2]);
            mnew[i] = fmaxf(m_st[i], cm);
            corr[i] = __expf(m_st[i] - mnew[i]);
            m_st[i] = mnew[i];
        }
        float psum[4] = {0.f, 0.f, 0.f, 0.f};
#pragma unroll
        for (int mf = 0; mf < 2; mf++)
#pragma unroll
            for (int hh2 = 0; hh2 < 2; hh2++) {
                int i = mf * 2 + hh2;
                float p0 = __expf(sc[mf][2 * hh2]     - mnew[i]);
                float p1 = __expf(sc[mf][2 * hh2 + 1] - mnew[i]);
                psum[i] += p0 + p1;
                int row = mf * 16 + hh2 * 8 + g;
                *(half2*)&Ps[row * PSTH + sl + 2 * t] = __floats2half2_rn(p0, p1);
            }
#pragma unroll
        for (int i = 0; i < 4; i++) {
            psum[i] += __shfl_xor_sync(0xffffffffu, psum[i], 1);
            psum[i] += __shfl_xor_sync(0xffffffffu, psum[i], 2);
        }
        if (t == 0)
#pragma unroll
            for (int i = 0; i < 4; i++)
                redsum[(i >> 1) * 16 + (i & 1) * 8 + g][w] = psum[i];
        __syncthreads();

#pragma unroll
        for (int i = 0; i < 4; i++) {
            int row = (i >> 1) * 16 + (i & 1) * 8 + g;
            float tot = 0.f;
#pragma unroll
            for (int w2 = 0; w2 < 8; w2++) tot += redsum[row][w2];
            l_st[i] = l_st[i] * corr[i] + tot;
        }
#pragma unroll
        for (int mf = 0; mf < 2; mf++)
#pragma unroll
            for (int idx = 0; idx < 4; idx++)
                co[mf][idx] *= corr[mf * 2 + (idx >> 1)];
        // ---- PV: warp owns d slice [sl, sl+8); B frags via ldmatrix.trans ----
#pragma unroll
        for (int kk = 0; kk < 4; kk++) {
            int kb = kk * 16;
            uint32_t bf[2];
            ldsm2t(bf, vsBase + ((uint32_t)(kb + (lane & 15)) * VSTH + sl) * 2);
#pragma unroll
            for (int mf = 0; mf < 2; mf++) {
                uint32_t af[4];
                int rm = mf * 16;
                af[0] = *(const uint32_t*)&Ps[(rm + g) * PSTH + kb + 2 * t];
                af[1] = *(const uint32_t*)&Ps[(rm + g + 8) * PSTH + kb + 2 * t];
                af[2] = *(const uint32_t*)&Ps[(rm + g) * PSTH + kb + 2 * t + 8];
                af[3] = *(const uint32_t*)&Ps[(rm + g + 8) * PSTH + kb + 2 * t + 8];
                mma_f16(co[mf], af, bf);
            }
        }
    }

#pragma unroll
    for (int mf = 0; mf < 2; mf++)
#pragma unroll
        for (int h = 0; h < 2; h++) {
            int row = mf * 16 + 8 * h + g;
            int qg = (row < 16) ? (q0a + row) : (q0b + row - 16);
            float inv = 1.f / l_st[mf * 2 + h];
            *(half2*)&out[((size_t)bb * SS + qg) * DIM + hh * HD + sl + 2 * t] =
                __floats2half2_rn(co[mf][2 * h] * inv, co[mf][2 * h + 1] * inv);
        }
}

// ---------------- launch ----------------
extern "C" void kernel_launch(void* const* d_in, const int* in_sizes, int n_in,
                              void* d_out, int out_size) {
    const float* x        = (const float*)d_in[0];
    const float* c        = (const float*)d_in[1];
    const float* cosb     = (const float*)d_in[2];
    const float* sinb     = (const float*)d_in[3];
    /* d_in[4] = mask (recomputed analytically in-kernel) */
    const float* norm1_w  = (const float*)d_in[5];
    const float* qkv_w    = (const float*)d_in[6];
    const float* attn_w   = (const float*)d_in[7];
    const float* norm2_w  = (const float*)d_in[8];
    const float* mlp_w1   = (const float*)d_in[9];
    const float* mlp_b1   = (const float*)d_in[10];
    const float* mlp_w2   = (const float*)d_in[11];
    const float* mlp_b2   = (const float*)d_in[12];
    const float* adaLN_w  = (const float*)d_in[13];
    const float* adaLN_b  = (const float*)d_in[14];
    float* out = (float*)d_out;

    float *mods, *qkvb, *x2;
    __half *h16, *a16, *mlp16, *w16;
    cudaGetSymbolAddress((void**)&mods,  g_mods);
    cudaGetSymbolAddress((void**)&h16,   g_h16);
    cudaGetSymbolAddress((void**)&qkvb,  g_qkv);
    cudaGetSymbolAddress((void**)&a16,   g_a16);
    cudaGetSymbolAddress((void**)&x2,    g_x2);
    cudaGetSymbolAddress((void**)&mlp16, g_mlp16);
    cudaGetSymbolAddress((void**)&w16,   g_w16);

    cudaFuncSetAttribute(gemm_h_k, cudaFuncAttributeMaxDynamicSharedMemorySize, DYN_SMEM);

    // 0. convert weights to fp16 arena
    cvt_w_k<<<(W_TOT / 4 + 255) / 256, 256>>>(qkv_w, attn_w, mlp_w1, mlp_w2, w16);

    // 1. adaLN modulation vector
    adaln_k<<<(BB * MODS + 255) / 256, 256>>>(c, adaLN_w, adaLN_b, mods);

    // 2. norm1 + modulate -> fp16
    ln_mod_k<<<MTOT, 256>>>(x, norm1_w, mods, h16, 0, DIM);

    // 3. QKV projection + fused RoPE (mode 3) -> fp32 qkv
    gemm_h_k<<<dim3(3 * DIM / 128, MTOT / 128), 256, DYN_SMEM>>>(
        h16, w16 + W_QKV, qkvb, nullptr, MTOT, 3 * DIM, DIM,
        nullptr, nullptr, nullptr, 0, 3, cosb, sinb);

    // 4. Block-sparse flash attention (fp16 MMA) -> fp16 a
    attn_mma_k<<<dim3(64, BB * NH), 256>>>(qkvb, a16);

    // 5. attn-out projection + gate_msa + x residual -> fp32 x2
    gemm_h_k<<<dim3(DIM / 128, MTOT / 128), 256, DYN_SMEM>>>(
        a16, w16 + W_ATT, x2, nullptr, MTOT, DIM, DIM,
        nullptr, x, mods, 2 * DIM, 2, nullptr, nullptr);

    // 6. norm2 + modulate -> fp16
    ln_mod_k<<<MTOT, 256>>>(x2, norm2_w, mods, h16, 3 * DIM, 4 * DIM);

    // 7. MLP up + gelu (mode 1) -> fp16 mlp
    gemm_h_k<<<dim3(4 * DIM / 128, MTOT / 128), 256, DYN_SMEM>>>(
        h16, w16 + W_M1, nullptr, mlp16, MTOT, 4 * DIM, DIM,
        mlp_b1, nullptr, nullptr, 0, 1, nullptr, nullptr);

    // 8. MLP down + bias + gate_mlp + x2 residual -> d_out
    gemm_h_k<<<dim3(DIM / 128, MTOT / 128), 256, DYN_SMEM>>>(
        mlp16, w16 + W_M2, out, nullptr, MTOT, DIM, 4 * DIM,
        mlp_b2, x2, mods, 5 * DIM, 2, nullptr, nullptr);
}

// round 16
// speedup vs baseline: 1.3935x; 1.0055x over previous
#include <cuda_runtime.h>
#include <cuda_fp16.h>
#include <math.h>
#include <stdint.h>

#define BB 2
#define NHALF 1024
#define SS 2048
#define DIM 768
#define NH 12
#define HD 64
#define COND 128
#define BLK 16
#define MTOT (BB*SS)          // 4096
#define MODS (6*DIM)          // 4608

// weight arena offsets (halves)
#define W_QKV 0
#define W_ATT (W_QKV + 3*DIM*DIM)
#define W_M1  (W_ATT + DIM*DIM)
#define W_M2  (W_M1 + 4*DIM*DIM)
#define W_TOT (W_M2 + 4*DIM*DIM)

// ---------------- scratch (device globals; no allocation allowed) ----------------
__device__ float g_mods[BB*MODS];
__device__ __half g_h16[MTOT*DIM];
__device__ float g_qkv[(size_t)MTOT*3*DIM];
__device__ __half g_a16[MTOT*DIM];
__device__ float g_x2[MTOT*DIM];
__device__ __half g_mlp16[(size_t)MTOT*4*DIM];
__device__ __half g_w16[W_TOT];

// ---------------- helpers ----------------
__device__ __forceinline__ float gelu_tanh(float x) {
    float x3 = x * x * x;
    return 0.5f * x * (1.f + tanhf(0.7978845608028654f * (x + 0.044715f * x3)));
}
__device__ __forceinline__ void mma_f16(float c[4], const uint32_t a[4], const uint32_t b[2]) {
    asm volatile(
        "mma.sync.aligned.m16n8k16.row.col.f32.f16.f16.f32 "
        "{%0,%1,%2,%3},{%4,%5,%6,%7},{%8,%9},{%0,%1,%2,%3};"
        : "+f"(c[0]), "+f"(c[1]), "+f"(c[2]), "+f"(c[3])
        : "r"(a[0]), "r"(a[1]), "r"(a[2]), "r"(a[3]), "r"(b[0]), "r"(b[1]));
}
__device__ __forceinline__ void ldsm4(uint32_t r[4], uint32_t addr) {
    asm volatile("ldmatrix.sync.aligned.m8n8.x4.shared.b16 {%0,%1,%2,%3}, [%4];"
                 : "=r"(r[0]), "=r"(r[1]), "=r"(r[2]), "=r"(r[3]) : "r"(addr));
}
__device__ __forceinline__ void ldsm2t(uint32_t r[2], uint32_t addr) {
    asm volatile("ldmatrix.sync.aligned.m8n8.x2.trans.shared.b16 {%0,%1}, [%2];"
                 : "=r"(r[0]), "=r"(r[1]) : "r"(addr));
}
__device__ __forceinline__ void cp16(uint32_t dst, const void* src) {
    asm volatile("cp.async.cg.shared.global [%0], [%1], 16;\n" :: "r"(dst), "l"(src));
}

// ---------------- weight fp32 -> fp16 conversion ----------------
__global__ void cvt_w_k(const float* __restrict__ w0, const float* __restrict__ w1,
                        const float* __restrict__ w2, const float* __restrict__ w3,
                        __half* __restrict__ dst) {
    int i4 = (blockIdx.x * 256 + threadIdx.x) * 4;
    if (i4 >= W_TOT) return;
    const float* src; int off;
    if (i4 < W_ATT)      { src = w0; off = i4 - W_QKV; }
    else if (i4 < W_M1)  { src = w1; off = i4 - W_ATT; }
    else if (i4 < W_M2)  { src = w2; off = i4 - W_M1; }
    else                 { src = w3; off = i4 - W_M2; }
    float4 v = *(const float4*)&src[off];
    *(half2*)&dst[i4]     = __floats2half2_rn(v.x, v.y);
    *(half2*)&dst[i4 + 2] = __floats2half2_rn(v.z, v.w);
}

// ---------------- adaLN: mods = c @ W^T + b ----------------
__global__ void adaln_k(const float* __restrict__ c, const float* __restrict__ w,
                        const float* __restrict__ b, float* __restrict__ mods) {
    int j = blockIdx.x * blockDim.x + threadIdx.x;
    if (j >= BB * MODS) return;
    int bb = j / MODS;
    int n  = j % MODS;
    const float* cr = c + bb * COND;
    const float* wr = w + (size_t)n * COND;
    float acc = b[n];
#pragma unroll 8
    for (int k = 0; k < COND; k++) acc += cr[k] * wr[k];
    mods[j] = acc;
}

// ---------------- LayerNorm + modulate -> fp16 ----------------
__global__ void ln_mod_k(const float* __restrict__ x, const float* __restrict__ w,
                         const float* __restrict__ mods, __half* __restrict__ out,
                         int shift_off, int scale_off) {
    int row = blockIdx.x;
    int bb  = row / SS;
    const float* xr = x + (size_t)row * DIM;
    int tid = threadIdx.x;

    float s = 0.f, s2 = 0.f;
    for (int j = tid; j < DIM; j += blockDim.x) {
        float v = xr[j];
        s += v; s2 += v * v;
    }
#pragma unroll
    for (int o = 16; o; o >>= 1) {
        s  += __shfl_xor_sync(0xffffffffu, s,  o);
        s2 += __shfl_xor_sync(0xffffffffu, s2, o);
    }
    __shared__ float wsum[8], wsum2[8];
    __shared__ float s_mu, s_rv;
    if ((tid & 31) == 0) { wsum[tid >> 5] = s; wsum2[tid >> 5] = s2; }
    __syncthreads();
    if (tid == 0) {
        float t = 0.f, t2 = 0.f;
        for (int i = 0; i < 8; i++) { t += wsum[i]; t2 += wsum2[i]; }
        float mu = t / DIM;
        float var = t2 / DIM - mu * mu;
        s_mu = mu;
        s_rv = rsqrtf(var + 1e-5f);
    }
    __syncthreads();
    float mu = s_mu, rv = s_rv;
    const float* msh = mods + bb * MODS + shift_off;
    const float* msc = mods + bb * MODS + scale_off;
    __half* orow = out + (size_t)row * DIM;
    for (int j = tid; j < DIM; j += blockDim.x)
        orow[j] = __float2half((xr[j] - mu) * rv * w[j] * (1.f + msc[j]) + msh[j]);
}

// ---------------- fp16 TC GEMM, templated block-M (128 or 64) ----------------
// BN=128, BK=64, 8 warps (2x4), 2-stage cp.async ring, 1 sync/iter.
// warp tile: (BM/2) x 32, strided n-octets {wn*8, +32, +64, +96}.
#define AST 72                 // halves per smem row (144B pitch, LDSM conflict-free)

template<int BM>
__global__ __launch_bounds__(256, 2) void gemm_h_k(
    const __half* __restrict__ A, const __half* __restrict__ Bw,
    float* __restrict__ Cf, __half* __restrict__ Ch,
    int M, int Ncols, int K,
    const float* __restrict__ bias, const float* __restrict__ res,
    const float* __restrict__ mods, int gate_off, int mode,
    const float* __restrict__ cosb, const float* __restrict__ sinb) {
    constexpr int MT = BM / 32;                 // warp m-tiles of 16 rows
    constexpr int STG_A_T = BM * AST * 2;       // bytes, A per stage
    constexpr int STG_TOT_T = (BM + 128) * AST * 2;

    extern __shared__ __half dynsm[];
    int tid  = threadIdx.x;
    int wid  = tid >> 5, lane = tid & 31;
    int wm   = wid >> 2, wn = wid & 3;          // 2x4 warp grid
    int g    = lane >> 2, t = lane & 3;
    int m0   = blockIdx.y * BM, n0 = blockIdx.x * 128;

    uint32_t smBase = (uint32_t)__cvta_generic_to_shared(dynsm);

    int quad = lane >> 3, lr = lane & 7;
    int aRowOff = lr + (quad & 1) * 8;
    int aColOff = (quad >> 1) * 8;
    int bRowOff = wn * 8 + (quad >> 1) * 32 + lr;
    int bColOff = (quad & 1) * 8;

    float acc[MT][4][4];
#pragma unroll
    for (int i = 0; i < MT; i++)
#pragma unroll
        for (int j = 0; j < 4; j++)
#pragma unroll
            for (int r = 0; r < 4; r++) acc[i][j][r] = 0.f;

    int nIter = K >> 6;   // BK = 64
#define PREFETCH_T(it, s) {                                                         \
        int k0 = (it) << 6;                                                         \
        uint32_t aDst = smBase + (s) * STG_TOT_T;                                   \
        uint32_t bDst = aDst + STG_A_T;                                             \
        _Pragma("unroll")                                                           \
        for (int i = 0; i < BM / 32; i++) {                                         \
            int e = i * 256 + tid;                                                  \
            int r = e >> 3, cc = (e & 7) * 8;                                       \
            cp16(aDst + (r * AST + cc) * 2, A + (size_t)(m0 + r) * K + k0 + cc);    \
        }                                                                           \
        _Pragma("unroll")                                                           \
        for (int i = 0; i < 4; i++) {                                               \
            int e = i * 256 + tid;                                                  \
            int r = e >> 3, cc = (e & 7) * 8;                                       \
            cp16(bDst + (r * AST + cc) * 2, Bw + (size_t)(n0 + r) * K + k0 + cc);   \
        }                                                                           \
        asm volatile("cp.async.commit_group;\n");                                   \
    }

    PREFETCH_T(0, 0);
    for (int it = 0; it < nIter; it++) {
        asm volatile("cp.async.wait_group 0;\n");
        __syncthreads();
        if (it + 1 < nIter) PREFETCH_T(it + 1, (it + 1) & 1);

        uint32_t aS = smBase + (it & 1) * STG_TOT_T;
        uint32_t bS = aS + STG_A_T;
#pragma unroll
        for (int ks = 0; ks < 4; ks++) {
            int kb = ks * 16;
            uint32_t af[MT][4], bf[4][2];
#pragma unroll
            for (int mt = 0; mt < MT; mt++) {
                int r = wm * (BM / 2) + mt * 16 + aRowOff;
                ldsm4(af[mt], aS + (r * AST + kb + aColOff) * 2);
            }
#pragma unroll
            for (int p = 0; p < 2; p++) {
                uint32_t tmp[4];
                int r = p * 64 + bRowOff;
                ldsm4(tmp, bS + (r * AST + kb + bColOff) * 2);
                bf[2 * p][0] = tmp[0]; bf[2 * p][1] = tmp[1];
                bf[2 * p + 1][0] = tmp[2]; bf[2 * p + 1][1] = tmp[3];
            }
#pragma unroll
            for (int mt = 0; mt < MT; mt++)
#pragma unroll
                for (int nt = 0; nt < 4; nt++) mma_f16(acc[mt][nt], af[mt], bf[nt]);
        }
    }

    // ---- epilogue ----
#pragma unroll
    for (int mt = 0; mt < MT; mt++) {
#pragma unroll
        for (int half_ = 0; half_ < 2; half_++) {
            int m = m0 + wm * (BM / 2) + mt * 16 + half_ * 8 + g;
            int bb = m / SS;
            if (mode == 3) {
                int stok = m & (SS - 1);
#pragma unroll
                for (int p = 0; p < 2; p++) {
                    int d0 = wn * 8 + 2 * t;
                    int n = n0 + p * 64 + d0;
                    float y1[2], y2[2];
#pragma unroll
                    for (int j = 0; j < 2; j++) {
                        float x1 = acc[mt][2 * p][half_ * 2 + j];
                        float x2 = acc[mt][2 * p + 1][half_ * 2 + j];
                        float c1 = cosb[stok * HD + d0 + j];
                        float s1 = sinb[stok * HD + d0 + j];
                        float c2 = cosb[stok * HD + d0 + j + 32];
                        float s2 = sinb[stok * HD + d0 + j + 32];
                        y1[j] = x1 * c1 - x2 * s1;
                        y2[j] = x2 * c2 + x1 * s2;
                    }
                    *(float2*)&Cf[(size_t)m * Ncols + n]      = make_float2(y1[0], y1[1]);
                    *(float2*)&Cf[(size_t)m * Ncols + n + 32] = make_float2(y2[0], y2[1]);
                }
            } else {
#pragma unroll
                for (int nt = 0; nt < 4; nt++) {
                    int n = n0 + wn * 8 + (nt & 1) * 32 + (nt >> 1) * 64 + 2 * t;
                    float v0 = acc[mt][nt][half_ * 2 + 0];
                    float v1 = acc[mt][nt][half_ * 2 + 1];
                    if (mode == 1) {
                        v0 = gelu_tanh(v0 + bias[n]);
                        v1 = gelu_tanh(v1 + bias[n + 1]);
                        *(half2*)&Ch[(size_t)m * Ncols + n] = __floats2half2_rn(v0, v1);
                    } else {  // mode 2
                        if (bias) { v0 += bias[n]; v1 += bias[n + 1]; }
                        float g0 = mods[bb * MODS + gate_off + n];
                        float g1 = mods[bb * MODS + gate_off + n + 1];
                        v0 = res[(size_t)m * Ncols + n]     + g0 * v0;
                        v1 = res[(size_t)m * Ncols + n + 1] + g1 * v1;
                        *(float2*)&Cf[(size_t)m * Ncols + n] = make_float2(v0, v1);
                    }
                }
            }
        }
    }
}

#define DYN_SMEM_128 ((128 + 128) * AST * 2 * 2)   // 73728 B
#define DYN_SMEM_64  ((64 + 128) * AST * 2 * 2)    // 55296 B

// ---------------- Block-sparse flash attention (fp16 MMA, V linear + ldsm2t) ----------------
#define QSTH 72
#define KSTH 72
#define PSTH 72
#define VSTH 72   // V pitch, layout [key][d]

__global__ __launch_bounds__(256) void attn_mma_k(const float* __restrict__ qkv,
                                                  __half* __restrict__ out) {
    int blkq = 63 - blockIdx.x;          // heavy CTAs first
    int bh = blockIdx.y;
    int bb = bh / NH, hh = bh % NH;
    int q0a = blkq * BLK;
    int q0b = NHALF + blkq * BLK;

    __shared__ __half Qs[32 * QSTH];
    __shared__ __half Ks[64 * KSTH];     // P (32 x PSTH) aliases after QK reads
    __shared__ __half Vs[64 * VSTH];     // [key][d]
    __shared__ float redmax[32][9];
    __shared__ float redsum[32][9];
    __half* Ps = Ks;
    uint32_t vsBase = (uint32_t)__cvta_generic_to_shared(Vs);

    int tid = threadIdx.x;
    int w = tid >> 5, lane = tid & 31;
    int g = lane >> 2, t = lane & 3;
    int sl = w * 8;

    for (int e = tid; e < 32 * 16; e += 256) {
        int r = e >> 4, d4 = (e & 15) * 4;
        int qg = (r < 16) ? (q0a + r) : (q0b + r - 16);
        float4 v = *(const float4*)&qkv[((((size_t)bb * SS + qg) * 3 + 0) * NH + hh) * HD + d4];
        *(half2*)&Qs[r * QSTH + d4]     = __floats2half2_rn(v.x, v.y);
        *(half2*)&Qs[r * QSTH + d4 + 2] = __floats2half2_rn(v.z, v.w);
    }

    float m_st[4], l_st[4];
#pragma unroll
    for (int i = 0; i < 4; i++) { m_st[i] = -1e30f; l_st[i] = 0.f; }
    float co[2][4] = {};

    int nch = 1 + (blkq * BLK + 63) / 64;
    for (int ch = 0; ch < nch; ch++) {
        int len = (ch == 0) ? 32 : min(64, blkq * BLK - (ch - 1) * 64);
        __syncthreads();
        for (int e = tid; e < len * 16; e += 256) {
            int r = e >> 4, d4 = (e & 15) * 4;
            int kg = (ch == 0) ? ((r < 16) ? (q0a + r) : (q0b + r - 16))
                               : (NHALF + (ch - 1) * 64 + r);
            size_t gb = (((size_t)bb * SS + kg) * 3) * NH * HD + (size_t)hh * HD + d4;
            float4 kv = *(const float4*)&qkv[gb + (size_t)NH * HD];
            float4 vv = *(const float4*)&qkv[gb + (size_t)2 * NH * HD];
            *(half2*)&Ks[r * KSTH + d4]     = __floats2half2_rn(kv.x, kv.y);
            *(half2*)&Ks[r * KSTH + d4 + 2] = __floats2half2_rn(kv.z, kv.w);
            half2 va = __floats2half2_rn(vv.x, vv.y);
            half2 vb = __floats2half2_rn(vv.z, vv.w);
            uint2 vpack = make_uint2(*(uint32_t*)&va, *(uint32_t*)&vb);
            *(uint2*)&Vs[r * VSTH + d4] = vpack;
        }
        if (len < 64) {   // zero V pad rows
            for (int e = tid; e < (64 - len) * 16; e += 256) {
                int r = len + (e >> 4), d4 = (e & 15) * 4;
                *(uint2*)&Vs[r * VSTH + d4] = make_uint2(0, 0);
            }
        }
        __syncthreads();

        float cqk[2][4] = {};
#pragma unroll
        for (int kd = 0; kd < 4; kd++) {
            int kb = kd * 16;
            uint32_t bf[2];
            bf[0] = *(const uint32_t*)&Ks[(sl + g) * KSTH + kb + 2 * t];
            bf[1] = *(const uint32_t*)&Ks[(sl + g) * KSTH + kb + 2 * t + 8];
#pragma unroll
            for (int mf = 0; mf < 2; mf++) {
                uint32_t af[4];
                int rm = mf * 16;
                af[0] = *(const uint32_t*)&Qs[(rm + g) * QSTH + kb + 2 * t];
                af[1] = *(const uint32_t*)&Qs[(rm + g + 8) * QSTH + kb + 2 * t];
                af[2] = *(const uint32_t*)&Qs[(rm + g) * QSTH + kb + 2 * t + 8];
                af[3] = *(const uint32_t*)&Qs[(rm + g + 8) * QSTH + kb + 2 * t + 8];
                mma_f16(cqk[mf], af, bf);
            }
        }
        float sc[2][4];
#pragma unroll
        for (int mf = 0; mf < 2; mf++)
#pragma unroll
            for (int idx = 0; idx < 4; idx++) {
                int key = sl + 2 * t + (idx & 1);
                int row = mf * 16 + g + 8 * (idx >> 1);
                bool valid = (ch == 0) ? ((key < 32) && ((row < 16) == (key < 16)))
                                       : (key < len);
                sc[mf][idx] = valid ? cqk[mf][idx] * 0.125f : -1e30f;
            }
        float rmax[4];
#pragma unroll
        for (int mf = 0; mf < 2; mf++)
#pragma unroll
            for (int h = 0; h < 2; h++)
                rmax[mf * 2 + h] = fmaxf(sc[mf][2 * h], sc[mf][2 * h + 1]);
#pragma unroll
        for (int i = 0; i < 4; i++) {
            rmax[i] = fmaxf(rmax[i], __shfl_xor_sync(0xffffffffu, rmax[i], 1));
            rmax[i] = fmaxf(rmax[i], __shfl_xor_sync(0xffffffffu, rmax[i], 2));
        }
        if (t == 0)
#pragma unroll
            for (int i = 0; i < 4; i++)
                redmax[(i >> 1) * 16 + (i & 1) * 8 + g][w] = rmax[i];
        __syncthreads();

        float mnew[4], corr[4];
#pragma unroll
        for (int i = 0; i < 4; i++) {
            int row = (i >> 1) * 16 + (i & 1) * 8 + g;
            float cm = -1e30f;
#pragma unroll
            for (int w2 = 0; w2 < 8; w2++) cm = fmaxf(cm, redmax[row][w2]);
            mnew[i] = fmaxf(m_st[i], cm);
            corr[i] = __expf(m_st[i] - mnew[i]);
            m_st[i] = mnew[i];
        }
        float psum[4] = {0.f, 0.f, 0.f, 0.f};
#pragma unroll
        for (int mf = 0; mf < 2; mf++)
#pragma unroll
            for (int hh2 = 0; hh2 < 2; hh2++) {
                int i = mf * 2 + hh2;
                float p0 = __expf(sc[mf][2 * hh2]     - mnew[i]);
                float p1 = __expf(sc[mf][2 * hh2 + 1] - mnew[i]);
                psum[i] += p0 + p1;
                int row = mf * 16 + hh2 * 8 + g;
                *(half2*)&Ps[row * PSTH + sl + 2 * t] = __floats2half2_rn(p0, p1);
            }
#pragma unroll
        for (int i = 0; i < 4; i++) {
            psum[i] += __shfl_xor_sync(0xffffffffu, psum[i], 1);
            psum[i] += __shfl_xor_sync(0xffffffffu, psum[i], 2);
        }
        if (t == 0)
#pragma unroll
            for (int i = 0; i < 4; i++)
                redsum[(i >> 1) * 16 + (i & 1) * 8 + g][w] = psum[i];
        __syncthreads();

#pragma unroll
        for (int i = 0; i < 4; i++) {
            int row = (i >> 1) * 16 + (i & 1) * 8 + g;
            float tot = 0.f;
#pragma unroll
            for (int w2 = 0; w2 < 8; w2++) tot += redsum[row][w2];
            l_st[i] = l_st[i] * corr[i] + tot;
        }
#pragma unroll
        for (int mf = 0; mf < 2; mf++)
#pragma unroll
            for (int idx = 0; idx < 4; idx++)
                co[mf][idx] *= corr[mf * 2 + (idx >> 1)];
#pragma unroll
        for (int kk = 0; kk < 4; kk++) {
            int kb = kk * 16;
            uint32_t bf[2];
            ldsm2t(bf, vsBase + ((uint32_t)(kb + (lane & 15)) * VSTH + sl) * 2);
#pragma unroll
            for (int mf = 0; mf < 2; mf++) {
                uint32_t af[4];
                int rm = mf * 16;
                af[0] = *(const uint32_t*)&Ps[(rm + g) * PSTH + kb + 2 * t];
                af[1] = *(const uint32_t*)&Ps[(rm + g + 8) * PSTH + kb + 2 * t];
                af[2] = *(const uint32_t*)&Ps[(rm + g) * PSTH + kb + 2 * t + 8];
                af[3] = *(const uint32_t*)&Ps[(rm + g + 8) * PSTH + kb + 2 * t + 8];
                mma_f16(co[mf], af, bf);
            }
        }
    }

#pragma unroll
    for (int mf = 0; mf < 2; mf++)
#pragma unroll
        for (int h = 0; h < 2; h++) {
            int row = mf * 16 + 8 * h + g;
            int qg = (row < 16) ? (q0a + row) : (q0b + row - 16);
            float inv = 1.f / l_st[mf * 2 + h];
            *(half2*)&out[((size_t)bb * SS + qg) * DIM + hh * HD + sl + 2 * t] =
                __floats2half2_rn(co[mf][2 * h] * inv, co[mf][2 * h + 1] * inv);
        }
}

// ---------------- launch ----------------
extern "C" void kernel_launch(void* const* d_in, const int* in_sizes, int n_in,
                              void* d_out, int out_size) {
    const float* x        = (const float*)d_in[0];
    const float* c        = (const float*)d_in[1];
    const float* cosb     = (const float*)d_in[2];
    const float* sinb     = (const float*)d_in[3];
    /* d_in[4] = mask (recomputed analytically in-kernel) */
    const float* norm1_w  = (const float*)d_in[5];
    const float* qkv_w    = (const float*)d_in[6];
    const float* attn_w   = (const float*)d_in[7];
    const float* norm2_w  = (const float*)d_in[8];
    const float* mlp_w1   = (const float*)d_in[9];
    const float* mlp_b1   = (const float*)d_in[10];
    const float* mlp_w2   = (const float*)d_in[11];
    const float* mlp_b2   = (const float*)d_in[12];
    const float* adaLN_w  = (const float*)d_in[13];
    const float* adaLN_b  = (const float*)d_in[14];
    float* out = (float*)d_out;

    float *mods, *qkvb, *x2;
    __half *h16, *a16, *mlp16, *w16;
    cudaGetSymbolAddress((void**)&mods,  g_mods);
    cudaGetSymbolAddress((void**)&h16,   g_h16);
    cudaGetSymbolAddress((void**)&qkvb,  g_qkv);
    cudaGetSymbolAddress((void**)&a16,   g_a16);
    cudaGetSymbolAddress((void**)&x2,    g_x2);
    cudaGetSymbolAddress((void**)&mlp16, g_mlp16);
    cudaGetSymbolAddress((void**)&w16,   g_w16);

    cudaFuncSetAttribute(gemm_h_k<128>, cudaFuncAttributeMaxDynamicSharedMemorySize, DYN_SMEM_128);
    cudaFuncSetAttribute(gemm_h_k<64>,  cudaFuncAttributeMaxDynamicSharedMemorySize, DYN_SMEM_64);

    // 0. convert weights to fp16 arena
    cvt_w_k<<<(W_TOT / 4 + 255) / 256, 256>>>(qkv_w, attn_w, mlp_w1, mlp_w2, w16);

    // 1. adaLN modulation vector
    adaln_k<<<(BB * MODS + 255) / 256, 256>>>(c, adaLN_w, adaLN_b, mods);

    // 2. norm1 + modulate -> fp16
    ln_mod_k<<<MTOT, 256>>>(x, norm1_w, mods, h16, 0, DIM);

    // 3. QKV projection + fused RoPE (mode 3) -> fp32 qkv   [BM=128]
    gemm_h_k<128><<<dim3(3 * DIM / 128, MTOT / 128), 256, DYN_SMEM_128>>>(
        h16, w16 + W_QKV, qkvb, nullptr, MTOT, 3 * DIM, DIM,
        nullptr, nullptr, nullptr, 0, 3, cosb, sinb);

    // 4. Block-sparse flash attention (fp16 MMA) -> fp16 a
    attn_mma_k<<<dim3(64, BB * NH), 256>>>(qkvb, a16);

    // 5. attn-out projection + gate_msa + x residual -> fp32 x2   [BM=64, 384 CTAs]
    gemm_h_k<64><<<dim3(DIM / 128, MTOT / 64), 256, DYN_SMEM_64>>>(
        a16, w16 + W_ATT, x2, nullptr, MTOT, DIM, DIM,
        nullptr, x, mods, 2 * DIM, 2, nullptr, nullptr);

    // 6. norm2 + modulate -> fp16
    ln_mod_k<<<MTOT, 256>>>(x2, norm2_w, mods, h16, 3 * DIM, 4 * DIM);

    // 7. MLP up + gelu (mode 1) -> fp16 mlp   [BM=128]
    gemm_h_k<128><<<dim3(4 * DIM / 128, MTOT / 128), 256, DYN_SMEM_128>>>(
        h16, w16 + W_M1, nullptr, mlp16, MTOT, 4 * DIM, DIM,
        mlp_b1, nullptr, nullptr, 0, 1, nullptr, nullptr);

    // 8. MLP down + bias + gate_mlp + x2 residual -> d_out   [BM=64, 384 CTAs]
    gemm_h_k<64><<<dim3(DIM / 128, MTOT / 64), 256, DYN_SMEM_64>>>(
        mlp16, w16 + W_M2, out, nullptr, MTOT, DIM, 4 * DIM,
        mlp_b2, x2, mods, 5 * DIM, 2, nullptr, nullptr);
}